// round 9
// baseline (speedup 1.0000x reference)
#include <cuda_runtime.h>
#include <cstdint>

// RevNet additive coupling: y1 = x1 ; y2 = x2 + x1 @ W
// x rows: [x1(128) | x2(128)] fp32, W: 128x128 fp32, 262144 rows.
//
// R9: bf16 m16n8k16 HMMA, FOUR independent 256-thread CTAs per SM
// (4 decoupled pipelines cover each other's barrier/DRAM stalls).
// 32-row tiles, fused convert-loader prefetched one tile ahead in
// registers, x2 prefetched to registers. Same verified R8 structure.

#define D 128
#define TILE_M 32
#define THREADS 256
#define SA 68    // X tile (bf16-pair words) row stride
#define SB 136   // W2 (bf16-pair words) row stride

static constexpr int ROWS_TOTAL = 262144;
static constexpr int NUM_TILES  = ROWS_TOTAL / TILE_M;    // 8192
static constexpr int W2_WORDS   = 64 * SB;                // 8704
static constexpr int XB_WORDS   = TILE_M * SA;            // 2176
static constexpr int SMEM_BYTES = (W2_WORDS + 2 * XB_WORDS) * 4;  // 52224

__device__ __forceinline__ uint32_t bfpack(float lo, float hi) {
    uint32_t r;
    asm("cvt.rn.bf16x2.f32 %0, %1, %2;" : "=r"(r) : "f"(hi), "f"(lo));
    return r;
}
__device__ __forceinline__ void mma_bf16(float& d0, float& d1, float& d2, float& d3,
                                         uint32_t a0, uint32_t a1, uint32_t a2, uint32_t a3,
                                         uint32_t b0, uint32_t b1) {
    asm volatile(
        "mma.sync.aligned.m16n8k16.row.col.f32.bf16.bf16.f32 "
        "{%0,%1,%2,%3}, {%4,%5,%6,%7}, {%8,%9}, {%0,%1,%2,%3};"
        : "+f"(d0), "+f"(d1), "+f"(d2), "+f"(d3)
        : "r"(a0), "r"(a1), "r"(a2), "r"(a3), "r"(b0), "r"(b1));
}

__global__ void __launch_bounds__(THREADS, 4)
revnet_bf16_kernel(const float* __restrict__ x,
                   const float* __restrict__ w,
                   float* __restrict__ out)
{
    extern __shared__ uint32_t smem[];
    uint32_t* W2 = smem;                         // [64 kp][SB]: {W[2kp][n], W[2kp+1][n]}
    uint32_t* XB[2] = { smem + W2_WORDS, smem + W2_WORDS + XB_WORDS };

    const int tid  = threadIdx.x;
    const int wid  = tid >> 5;
    const int lane = tid & 31;
    const int gid  = lane >> 2;          // 0..7
    const int tig  = lane & 3;           // 0..3
    const int slab  = (wid & 1) << 4;    // m-slab base (0, 16)
    const int nbase = (wid >> 1) << 5;   // n-group base (0,32,64,96)

    // Stage W2 (bf16 k-pairs, row kp = k/2, col n). One-time per CTA.
    for (int idx = tid; idx < 64 * D; idx += THREADS) {
        const int kp = idx >> 7, n = idx & 127;
        W2[kp * SB + n] = bfpack(w[(2 * kp) * D + n], w[(2 * kp + 1) * D + n]);
    }

    const int start   = blockIdx.x;
    const int gstride = gridDim.x;

    // Preamble: fill buffer 0 with tile `start` (also streams its y1).
    {
        const long rowbase = (long)start * TILE_M;
        #pragma unroll
        for (int p = 0; p < 4; p++) {
            const int  i = p * THREADS + tid;
            const int  r = i >> 5;
            const int  q = i & 31;
            const long g = (rowbase + r) * 256L + 4 * q;
            const float4 v = *(const float4*)(x + g);
            *(float4*)(out + g) = v;                      // y1 (exact fp32)
            XB[0][r * SA + 2 * q]     = bfpack(v.x, v.y);
            XB[0][r * SA + 2 * q + 1] = bfpack(v.z, v.w);
        }
    }
    __syncthreads();

    int buf = 0;
    for (int t = start; t < NUM_TILES; t += gstride, buf ^= 1) {
        const long rowbase = (long)t * TILE_M;
        const int  nt      = t + gstride;
        const bool hn      = nt < NUM_TILES;

        // Prefetch next tile's x1 into registers (consumed after mainloop).
        float4 pf[4];
        if (hn) {
            const long nb = (long)nt * TILE_M;
            #pragma unroll
            for (int p = 0; p < 4; p++) {
                const int i = p * THREADS + tid;
                pf[p] = *(const float4*)(x + (nb + (i >> 5)) * 256L + 4 * (i & 31));
            }
        }

        // Prefetch this tile's x2 into registers.
        const long r0 = rowbase + slab + gid;
        float2 x2a[4], x2b[4];
        #pragma unroll
        for (int j = 0; j < 4; j++) {
            const long g0 = r0 * 256L + 128 + nbase + 8 * j + 2 * tig;
            x2a[j] = *(const float2*)(x + g0);
            x2b[j] = *(const float2*)(x + g0 + 8 * 256L);
        }

        // Mainloop: 8 k-steps (K=16 each) x 4 n-tiles.
        float acc[4][4];
        #pragma unroll
        for (int j = 0; j < 4; j++)
            { acc[j][0] = 0.f; acc[j][1] = 0.f; acc[j][2] = 0.f; acc[j][3] = 0.f; }

        const uint32_t* xr0 = XB[buf] + (slab + gid) * SA;   // row gid of slab
        const uint32_t* xr1 = xr0 + 8 * SA;                  // row gid+8

        #pragma unroll
        for (int ks = 0; ks < 8; ks++) {
            const int kp = ks * 8;
            const uint32_t a0 = xr0[kp + tig];
            const uint32_t a1 = xr1[kp + tig];
            const uint32_t a2 = xr0[kp + 4 + tig];
            const uint32_t a3 = xr1[kp + 4 + tig];

            const uint32_t* b0p = W2 + (kp + tig) * SB + nbase + gid;
            const uint32_t* b1p = b0p + 4 * SB;
            #pragma unroll
            for (int j = 0; j < 4; j++) {
                mma_bf16(acc[j][0], acc[j][1], acc[j][2], acc[j][3],
                         a0, a1, a2, a3, b0p[8 * j], b1p[8 * j]);
            }
        }

        // Epilogue: y2 = x2 + acc (x2 already in registers; sector-exact STG.64).
        #pragma unroll
        for (int j = 0; j < 4; j++) {
            const long g0 = r0 * 256L + 128 + nbase + 8 * j + 2 * tig;
            float2 o0, o1;
            o0.x = x2a[j].x + acc[j][0];
            o0.y = x2a[j].y + acc[j][1];
            o1.x = x2b[j].x + acc[j][2];
            o1.y = x2b[j].y + acc[j][3];
            *(float2*)(out + g0) = o0;
            *(float2*)(out + g0 + 8 * 256L) = o1;
        }

        // Drain prefetch: y1 of next tile + convert into the other buffer.
        if (hn) {
            const long nb = (long)nt * TILE_M;
            uint32_t* Xn = XB[buf ^ 1];
            #pragma unroll
            for (int p = 0; p < 4; p++) {
                const int  i = p * THREADS + tid;
                const int  r = i >> 5;
                const int  q = i & 31;
                *(float4*)(out + (nb + r) * 256L + 4 * q) = pf[p];   // y1
                Xn[r * SA + 2 * q]     = bfpack(pf[p].x, pf[p].y);
                Xn[r * SA + 2 * q + 1] = bfpack(pf[p].z, pf[p].w);
            }
        }

        __syncthreads();   // next buffer complete; current buffer reads done
    }
}

extern "C" void kernel_launch(void* const* d_in, const int* in_sizes, int n_in,
                              void* d_out, int out_size)
{
    const float* x = (const float*)d_in[0];   // [8, 32768, 256] fp32
    const float* w = (const float*)d_in[1];   // [128, 128] fp32
    float* out = (float*)d_out;

    cudaFuncSetAttribute(revnet_bf16_kernel,
                         cudaFuncAttributeMaxDynamicSharedMemorySize,
                         SMEM_BYTES);

    // 4 CTAs per SM -> four decoupled pipelines per SM.
    revnet_bf16_kernel<<<592, THREADS, SMEM_BYTES>>>(x, w, out);
}

// round 10
// speedup vs baseline: 1.2913x; 1.2913x over previous
#include <cuda_runtime.h>
#include <cstdint>

// RevNet additive coupling: y1 = x1 ; y2 = x2 + x1 @ W
// x rows: [x1(128) | x2(128)] fp32, W: 128x128 fp32, 262144 rows.
//
// R10: bf16 m16n8k16 HMMA with W (B) FRAGMENTS PERSISTENT IN REGISTERS —
// W is constant across tiles, so the per-tile B-fragment LDS traffic
// (dominant L1 load in R8) is eliminated. W2 smem staging is consumed into
// registers once, then that smem is overlaid with the x-tile buffers.
// 3 CTAs x 256 threads per SM (3 decoupled pipelines), TILE_M=16.

#define D 128
#define TILE_M 16
#define THREADS 256
#define SA 68    // X tile (bf16-pair words) row stride
#define SB 136   // W2 staging (bf16-pair words) row stride

static constexpr int ROWS_TOTAL = 262144;
static constexpr int NUM_TILES  = ROWS_TOTAL / TILE_M;    // 16384
static constexpr int XB_WORDS   = TILE_M * SA;            // 1088
static constexpr int W2_WORDS   = 64 * SB;                // 8704 (staging)
static constexpr int SMEM_BYTES = W2_WORDS * 4;           // 34816 (X bufs overlay)

__device__ __forceinline__ uint32_t bfpack(float lo, float hi) {
    uint32_t r;
    asm("cvt.rn.bf16x2.f32 %0, %1, %2;" : "=r"(r) : "f"(hi), "f"(lo));
    return r;
}
__device__ __forceinline__ void mma_bf16(float& d0, float& d1, float& d2, float& d3,
                                         uint32_t a0, uint32_t a1, uint32_t a2, uint32_t a3,
                                         uint32_t b0, uint32_t b1) {
    asm volatile(
        "mma.sync.aligned.m16n8k16.row.col.f32.bf16.bf16.f32 "
        "{%0,%1,%2,%3}, {%4,%5,%6,%7}, {%8,%9}, {%0,%1,%2,%3};"
        : "+f"(d0), "+f"(d1), "+f"(d2), "+f"(d3)
        : "r"(a0), "r"(a1), "r"(a2), "r"(a3), "r"(b0), "r"(b1));
}

__global__ void __launch_bounds__(THREADS, 3)
revnet_bf16_kernel(const float* __restrict__ x,
                   const float* __restrict__ w,
                   float* __restrict__ out)
{
    extern __shared__ uint32_t smem[];

    const int tid  = threadIdx.x;
    const int wid  = tid >> 5;
    const int lane = tid & 31;
    const int gid  = lane >> 2;          // 0..7
    const int tig  = lane & 3;           // 0..3
    const int nbase = wid << 4;          // n-group base (16 cols per warp)

    // --- Stage W2 into smem (bf16 k-pairs: row kp=k/2, col n), one-time. ---
    uint32_t* W2 = smem;
    for (int idx = tid; idx < 64 * D; idx += THREADS) {
        const int kp = idx >> 7, n = idx & 127;
        W2[kp * SB + n] = bfpack(w[(2 * kp) * D + n], w[(2 * kp + 1) * D + n]);
    }
    __syncthreads();

    // --- Consume W2 into persistent per-thread B fragments. ---
    // Breg[ks][j][0] = pair(W[k0][n], W[k0+1][n]), k0 = 2*(8ks+tig),
    //                  n = nbase + 8*j + gid;  [1] is the kp+4 half.
    uint32_t Breg[8][2][2];
    #pragma unroll
    for (int ks = 0; ks < 8; ks++) {
        #pragma unroll
        for (int j = 0; j < 2; j++) {
            Breg[ks][j][0] = W2[(8 * ks + tig) * SB + nbase + 8 * j + gid];
            Breg[ks][j][1] = W2[(8 * ks + 4 + tig) * SB + nbase + 8 * j + gid];
        }
    }
    __syncthreads();   // all frag reads done -> smem region may be overlaid

    uint32_t* XB[2] = { smem, smem + XB_WORDS };   // overlay W2 staging

    const int start   = blockIdx.x;
    const int gstride = gridDim.x;

    // Preamble: fill buffer 0 with tile `start` (also streams its y1).
    {
        const long rowbase = (long)start * TILE_M;
        #pragma unroll
        for (int p = 0; p < 2; p++) {
            const int  i = p * THREADS + tid;
            const int  r = i >> 5;
            const int  q = i & 31;
            const long g = (rowbase + r) * 256L + 4 * q;
            const float4 v = *(const float4*)(x + g);
            *(float4*)(out + g) = v;                      // y1 (exact fp32)
            XB[0][r * SA + 2 * q]     = bfpack(v.x, v.y);
            XB[0][r * SA + 2 * q + 1] = bfpack(v.z, v.w);
        }
    }
    __syncthreads();

    int buf = 0;
    for (int t = start; t < NUM_TILES; t += gstride, buf ^= 1) {
        const long rowbase = (long)t * TILE_M;
        const int  nt      = t + gstride;
        const bool hn      = nt < NUM_TILES;

        // Prefetch next tile's x1 into registers (consumed after mainloop).
        float4 pf[2];
        if (hn) {
            const long nb = (long)nt * TILE_M;
            #pragma unroll
            for (int p = 0; p < 2; p++) {
                const int i = p * THREADS + tid;
                pf[p] = *(const float4*)(x + (nb + (i >> 5)) * 256L + 4 * (i & 31));
            }
        }

        // Prefetch this tile's x2 into registers.
        const long r0 = rowbase + gid;
        float2 x2a[2], x2b[2];
        #pragma unroll
        for (int j = 0; j < 2; j++) {
            const long g0 = r0 * 256L + 128 + nbase + 8 * j + 2 * tig;
            x2a[j] = *(const float2*)(x + g0);
            x2b[j] = *(const float2*)(x + g0 + 8 * 256L);
        }

        // Mainloop: 8 k-steps (K=16) x 2 n-tiles. B from registers, A from smem.
        float acc[2][4];
        #pragma unroll
        for (int j = 0; j < 2; j++)
            { acc[j][0] = 0.f; acc[j][1] = 0.f; acc[j][2] = 0.f; acc[j][3] = 0.f; }

        const uint32_t* xr0 = XB[buf] + gid * SA;    // A row gid
        const uint32_t* xr1 = xr0 + 8 * SA;          // A row gid+8

        #pragma unroll
        for (int ks = 0; ks < 8; ks++) {
            const int kp = ks * 8;
            const uint32_t a0 = xr0[kp + tig];
            const uint32_t a1 = xr1[kp + tig];
            const uint32_t a2 = xr0[kp + 4 + tig];
            const uint32_t a3 = xr1[kp + 4 + tig];
            #pragma unroll
            for (int j = 0; j < 2; j++) {
                mma_bf16(acc[j][0], acc[j][1], acc[j][2], acc[j][3],
                         a0, a1, a2, a3, Breg[ks][j][0], Breg[ks][j][1]);
            }
        }

        // Epilogue: y2 = x2 + acc (x2 in registers; sector-exact STG.64).
        #pragma unroll
        for (int j = 0; j < 2; j++) {
            const long g0 = r0 * 256L + 128 + nbase + 8 * j + 2 * tig;
            float2 o0, o1;
            o0.x = x2a[j].x + acc[j][0];
            o0.y = x2a[j].y + acc[j][1];
            o1.x = x2b[j].x + acc[j][2];
            o1.y = x2b[j].y + acc[j][3];
            *(float2*)(out + g0) = o0;
            *(float2*)(out + g0 + 8 * 256L) = o1;
        }

        // Drain prefetch: y1 of next tile + convert into the other buffer.
        if (hn) {
            const long nb = (long)nt * TILE_M;
            uint32_t* Xn = XB[buf ^ 1];
            #pragma unroll
            for (int p = 0; p < 2; p++) {
                const int  i = p * THREADS + tid;
                const int  r = i >> 5;
                const int  q = i & 31;
                *(float4*)(out + (nb + r) * 256L + 4 * q) = pf[p];   // y1
                Xn[r * SA + 2 * q]     = bfpack(pf[p].x, pf[p].y);
                Xn[r * SA + 2 * q + 1] = bfpack(pf[p].z, pf[p].w);
            }
        }

        __syncthreads();   // next buffer complete; current buffer reads done
    }
}

extern "C" void kernel_launch(void* const* d_in, const int* in_sizes, int n_in,
                              void* d_out, int out_size)
{
    const float* x = (const float*)d_in[0];   // [8, 32768, 256] fp32
    const float* w = (const float*)d_in[1];   // [128, 128] fp32
    float* out = (float*)d_out;

    cudaFuncSetAttribute(revnet_bf16_kernel,
                         cudaFuncAttributeMaxDynamicSharedMemorySize,
                         SMEM_BYTES);

    // 3 CTAs per SM -> three decoupled pipelines, W frags live in registers.
    revnet_bf16_kernel<<<444, THREADS, SMEM_BYTES>>>(x, w, out);
}

// round 11
// speedup vs baseline: 1.4477x; 1.1211x over previous
#include <cuda_runtime.h>
#include <cstdint>

// RevNet additive coupling: y1 = x1 ; y2 = x2 + x1 @ W
// x rows: [x1(128) | x2(128)] fp32, W: 128x128 fp32, 262144 rows.
//
// R11 = R10 (reg-resident W fragments, 3x256 CTAs, TILE_M=16, smem overlay)
// + x2 prefetched ONE ITERATION ahead (full-iteration latency cover, same regs)
// + ldmatrix.x4 for A fragments (32 LDS -> 8 LDSM per warp per tile).

#define D 128
#define TILE_M 16
#define THREADS 256
#define SA 68    // X tile (bf16-pair words) row stride
#define SB 136   // W2 staging (bf16-pair words) row stride

static constexpr int ROWS_TOTAL = 262144;
static constexpr int NUM_TILES  = ROWS_TOTAL / TILE_M;    // 16384
static constexpr int XB_WORDS   = TILE_M * SA;            // 1088
static constexpr int W2_WORDS   = 64 * SB;                // 8704 (staging)
static constexpr int SMEM_BYTES = W2_WORDS * 4;           // 34816 (X bufs overlay)

__device__ __forceinline__ uint32_t bfpack(float lo, float hi) {
    uint32_t r;
    asm("cvt.rn.bf16x2.f32 %0, %1, %2;" : "=r"(r) : "f"(hi), "f"(lo));
    return r;
}
__device__ __forceinline__ void mma_bf16(float& d0, float& d1, float& d2, float& d3,
                                         uint32_t a0, uint32_t a1, uint32_t a2, uint32_t a3,
                                         uint32_t b0, uint32_t b1) {
    asm volatile(
        "mma.sync.aligned.m16n8k16.row.col.f32.bf16.bf16.f32 "
        "{%0,%1,%2,%3}, {%4,%5,%6,%7}, {%8,%9}, {%0,%1,%2,%3};"
        : "+f"(d0), "+f"(d1), "+f"(d2), "+f"(d3)
        : "r"(a0), "r"(a1), "r"(a2), "r"(a3), "r"(b0), "r"(b1));
}
__device__ __forceinline__ void ldsm_x4(uint32_t& a0, uint32_t& a1,
                                        uint32_t& a2, uint32_t& a3, uint32_t addr) {
    asm volatile("ldmatrix.sync.aligned.m8n8.x4.shared.b16 {%0,%1,%2,%3}, [%4];"
                 : "=r"(a0), "=r"(a1), "=r"(a2), "=r"(a3) : "r"(addr));
}

__global__ void __launch_bounds__(THREADS, 3)
revnet_bf16_kernel(const float* __restrict__ x,
                   const float* __restrict__ w,
                   float* __restrict__ out)
{
    extern __shared__ uint32_t smem[];

    const int tid  = threadIdx.x;
    const int wid  = tid >> 5;
    const int lane = tid & 31;
    const int gid  = lane >> 2;          // 0..7
    const int tig  = lane & 3;           // 0..3
    const int nbase = wid << 4;          // n-group base (16 cols per warp)

    // --- Stage W2 into smem (bf16 k-pairs: row kp=k/2, col n), one-time. ---
    uint32_t* W2 = smem;
    for (int idx = tid; idx < 64 * D; idx += THREADS) {
        const int kp = idx >> 7, n = idx & 127;
        W2[kp * SB + n] = bfpack(w[(2 * kp) * D + n], w[(2 * kp + 1) * D + n]);
    }
    __syncthreads();

    // --- Consume W2 into persistent per-thread B fragments. ---
    uint32_t Breg[8][2][2];
    #pragma unroll
    for (int ks = 0; ks < 8; ks++) {
        #pragma unroll
        for (int j = 0; j < 2; j++) {
            Breg[ks][j][0] = W2[(8 * ks + tig) * SB + nbase + 8 * j + gid];
            Breg[ks][j][1] = W2[(8 * ks + 4 + tig) * SB + nbase + 8 * j + gid];
        }
    }
    __syncthreads();   // frag reads done -> smem region overlaid below

    uint32_t* XB[2] = { smem, smem + XB_WORDS };   // overlay W2 staging

    // ldmatrix per-lane base addresses (bytes) into each buffer:
    // lanes 0-7: rows 0-7 k0 | 8-15: rows 8-15 k0 | 16-23: rows 0-7 k8 | 24-31: rows 8-15 k8
    const uint32_t lrow = lane & 15;
    const uint32_t lkof = (lane >> 4) << 2;        // +4 words = +8 k
    const uint32_t ab0 = (uint32_t)__cvta_generic_to_shared(XB[0]) + (lrow * SA + lkof) * 4;
    const uint32_t ab1 = (uint32_t)__cvta_generic_to_shared(XB[1]) + (lrow * SA + lkof) * 4;

    const int start   = blockIdx.x;
    const int gstride = gridDim.x;

    // Preamble: fill buffer 0 with tile `start` (streams its y1) and load
    // x2 registers for tile `start`.
    {
        const long rowbase = (long)start * TILE_M;
        #pragma unroll
        for (int p = 0; p < 2; p++) {
            const int  i = p * THREADS + tid;
            const int  r = i >> 5;
            const int  q = i & 31;
            const long g = (rowbase + r) * 256L + 4 * q;
            const float4 v = *(const float4*)(x + g);
            *(float4*)(out + g) = v;                      // y1 (exact fp32)
            XB[0][r * SA + 2 * q]     = bfpack(v.x, v.y);
            XB[0][r * SA + 2 * q + 1] = bfpack(v.z, v.w);
        }
    }
    float2 x2a[2], x2b[2];
    {
        const long r0s = (long)start * TILE_M + gid;
        #pragma unroll
        for (int j = 0; j < 2; j++) {
            const long g0 = r0s * 256L + 128 + nbase + 8 * j + 2 * tig;
            x2a[j] = *(const float2*)(x + g0);
            x2b[j] = *(const float2*)(x + g0 + 8 * 256L);
        }
    }
    __syncthreads();

    int buf = 0;
    for (int t = start; t < NUM_TILES; t += gstride, buf ^= 1) {
        const long rowbase = (long)t * TILE_M;
        const int  nt      = t + gstride;
        const bool hn      = nt < NUM_TILES;

        // Prefetch next tile's x1 into registers (consumed in drain phase).
        float4 pf[2];
        if (hn) {
            const long nb = (long)nt * TILE_M;
            #pragma unroll
            for (int p = 0; p < 2; p++) {
                const int i = p * THREADS + tid;
                pf[p] = *(const float4*)(x + (nb + (i >> 5)) * 256L + 4 * (i & 31));
            }
        }

        // Mainloop: 8 k-steps (K=16) x 2 n-tiles. B in regs, A via ldmatrix.
        float acc[2][4];
        #pragma unroll
        for (int j = 0; j < 2; j++)
            { acc[j][0] = 0.f; acc[j][1] = 0.f; acc[j][2] = 0.f; acc[j][3] = 0.f; }

        const uint32_t ab = buf ? ab1 : ab0;
        #pragma unroll
        for (int ks = 0; ks < 8; ks++) {
            uint32_t a0, a1, a2, a3;
            ldsm_x4(a0, a1, a2, a3, ab + ks * 32);
            #pragma unroll
            for (int j = 0; j < 2; j++) {
                mma_bf16(acc[j][0], acc[j][1], acc[j][2], acc[j][3],
                         a0, a1, a2, a3, Breg[ks][j][0], Breg[ks][j][1]);
            }
        }

        // Epilogue: y2 = x2 + acc (x2 prefetched LAST iteration; STG.64).
        const long r0 = rowbase + gid;
        #pragma unroll
        for (int j = 0; j < 2; j++) {
            const long g0 = r0 * 256L + 128 + nbase + 8 * j + 2 * tig;
            float2 o0, o1;
            o0.x = x2a[j].x + acc[j][0];
            o0.y = x2a[j].y + acc[j][1];
            o1.x = x2b[j].x + acc[j][2];
            o1.y = x2b[j].y + acc[j][3];
            *(float2*)(out + g0) = o0;
            *(float2*)(out + g0 + 8 * 256L) = o1;
        }

        // Prefetch NEXT tile's x2 (consumed next iteration; full-loop cover).
        if (hn) {
            const long r0n = (long)nt * TILE_M + gid;
            #pragma unroll
            for (int j = 0; j < 2; j++) {
                const long g0 = r0n * 256L + 128 + nbase + 8 * j + 2 * tig;
                x2a[j] = *(const float2*)(x + g0);
                x2b[j] = *(const float2*)(x + g0 + 8 * 256L);
            }
        }

        // Drain prefetch: y1 of next tile + convert into the other buffer.
        if (hn) {
            const long nb = (long)nt * TILE_M;
            uint32_t* Xn = XB[buf ^ 1];
            #pragma unroll
            for (int p = 0; p < 2; p++) {
                const int  i = p * THREADS + tid;
                const int  r = i >> 5;
                const int  q = i & 31;
                *(float4*)(out + (nb + r) * 256L + 4 * q) = pf[p];   // y1
                Xn[r * SA + 2 * q]     = bfpack(pf[p].x, pf[p].y);
                Xn[r * SA + 2 * q + 1] = bfpack(pf[p].z, pf[p].w);
            }
        }

        __syncthreads();   // next buffer complete; current buffer reads done
    }
}

extern "C" void kernel_launch(void* const* d_in, const int* in_sizes, int n_in,
                              void* d_out, int out_size)
{
    const float* x = (const float*)d_in[0];   // [8, 32768, 256] fp32
    const float* w = (const float*)d_in[1];   // [128, 128] fp32
    float* out = (float*)d_out;

    cudaFuncSetAttribute(revnet_bf16_kernel,
                         cudaFuncAttributeMaxDynamicSharedMemorySize,
                         SMEM_BYTES);

    // 3 CTAs per SM, W frags in registers, deep x2 prefetch.
    revnet_bf16_kernel<<<444, THREADS, SMEM_BYTES>>>(x, w, out);
}

// round 12
// speedup vs baseline: 1.5552x; 1.0743x over previous
#include <cuda_runtime.h>
#include <cstdint>

// RevNet additive coupling: y1 = x1 ; y2 = x2 + x1 @ W
// x rows: [x1(128) | x2(128)] fp32, W: 128x128 fp32, 262144 rows.
//
// R12 = R11 (reg-resident W frags, 3x256 CTAs, TILE_M=16, ldmatrix A,
// smem overlay) with the x1 pipeline SKEWED ONE ITERATION: the prefetch
// registers survive the barrier, so every x1 LDG has a full iteration of
// cover instead of just the mainloop. Loop order per iteration t:
//   drain(t+1 from pf) -> issue LDG(t+2)->pf -> mainloop(t) -> epilogue(t)
//   -> x2 LDG(t+1) -> barrier.

#define D 128
#define TILE_M 16
#define THREADS 256
#define SA 68    // X tile (bf16-pair words) row stride
#define SB 136   // W2 staging (bf16-pair words) row stride

static constexpr int ROWS_TOTAL = 262144;
static constexpr int NUM_TILES  = ROWS_TOTAL / TILE_M;    // 16384
static constexpr int XB_WORDS   = TILE_M * SA;            // 1088
static constexpr int W2_WORDS   = 64 * SB;                // 8704 (staging)
static constexpr int SMEM_BYTES = W2_WORDS * 4;           // 34816 (X bufs overlay)

__device__ __forceinline__ uint32_t bfpack(float lo, float hi) {
    uint32_t r;
    asm("cvt.rn.bf16x2.f32 %0, %1, %2;" : "=r"(r) : "f"(hi), "f"(lo));
    return r;
}
__device__ __forceinline__ void mma_bf16(float& d0, float& d1, float& d2, float& d3,
                                         uint32_t a0, uint32_t a1, uint32_t a2, uint32_t a3,
                                         uint32_t b0, uint32_t b1) {
    asm volatile(
        "mma.sync.aligned.m16n8k16.row.col.f32.bf16.bf16.f32 "
        "{%0,%1,%2,%3}, {%4,%5,%6,%7}, {%8,%9}, {%0,%1,%2,%3};"
        : "+f"(d0), "+f"(d1), "+f"(d2), "+f"(d3)
        : "r"(a0), "r"(a1), "r"(a2), "r"(a3), "r"(b0), "r"(b1));
}
__device__ __forceinline__ void ldsm_x4(uint32_t& a0, uint32_t& a1,
                                        uint32_t& a2, uint32_t& a3, uint32_t addr) {
    asm volatile("ldmatrix.sync.aligned.m8n8.x4.shared.b16 {%0,%1,%2,%3}, [%4];"
                 : "=r"(a0), "=r"(a1), "=r"(a2), "=r"(a3) : "r"(addr));
}

__global__ void __launch_bounds__(THREADS, 3)
revnet_bf16_kernel(const float* __restrict__ x,
                   const float* __restrict__ w,
                   float* __restrict__ out)
{
    extern __shared__ uint32_t smem[];

    const int tid  = threadIdx.x;
    const int wid  = tid >> 5;
    const int lane = tid & 31;
    const int gid  = lane >> 2;          // 0..7
    const int tig  = lane & 3;           // 0..3
    const int nbase = wid << 4;          // n-group base (16 cols per warp)

    // --- Stage W2 into smem (bf16 k-pairs: row kp=k/2, col n), one-time. ---
    uint32_t* W2 = smem;
    for (int idx = tid; idx < 64 * D; idx += THREADS) {
        const int kp = idx >> 7, n = idx & 127;
        W2[kp * SB + n] = bfpack(w[(2 * kp) * D + n], w[(2 * kp + 1) * D + n]);
    }
    __syncthreads();

    // --- Consume W2 into persistent per-thread B fragments. ---
    uint32_t Breg[8][2][2];
    #pragma unroll
    for (int ks = 0; ks < 8; ks++) {
        #pragma unroll
        for (int j = 0; j < 2; j++) {
            Breg[ks][j][0] = W2[(8 * ks + tig) * SB + nbase + 8 * j + gid];
            Breg[ks][j][1] = W2[(8 * ks + 4 + tig) * SB + nbase + 8 * j + gid];
        }
    }
    __syncthreads();   // frag reads done -> smem region overlaid below

    uint32_t* XB[2] = { smem, smem + XB_WORDS };   // overlay W2 staging

    // ldmatrix per-lane base addresses (bytes) into each buffer.
    const uint32_t lrow = lane & 15;
    const uint32_t lkof = (lane >> 4) << 2;        // +4 words = +8 k
    const uint32_t ab0 = (uint32_t)__cvta_generic_to_shared(XB[0]) + (lrow * SA + lkof) * 4;
    const uint32_t ab1 = (uint32_t)__cvta_generic_to_shared(XB[1]) + (lrow * SA + lkof) * 4;

    const int start   = blockIdx.x;
    const int gstride = gridDim.x;

    // Preamble: tile `start` directly into XB[0] (streams its y1), x2 regs
    // for `start`, and pf <- x1 of tile start+gstride.
    {
        const long rowbase = (long)start * TILE_M;
        #pragma unroll
        for (int p = 0; p < 2; p++) {
            const int  i = p * THREADS + tid;
            const int  r = i >> 5;
            const int  q = i & 31;
            const long g = (rowbase + r) * 256L + 4 * q;
            const float4 v = *(const float4*)(x + g);
            *(float4*)(out + g) = v;                      // y1 (exact fp32)
            XB[0][r * SA + 2 * q]     = bfpack(v.x, v.y);
            XB[0][r * SA + 2 * q + 1] = bfpack(v.z, v.w);
        }
    }
    float2 x2a[2], x2b[2];
    {
        const long r0s = (long)start * TILE_M + gid;
        #pragma unroll
        for (int j = 0; j < 2; j++) {
            const long g0 = r0s * 256L + 128 + nbase + 8 * j + 2 * tig;
            x2a[j] = *(const float2*)(x + g0);
            x2b[j] = *(const float2*)(x + g0 + 8 * 256L);
        }
    }
    float4 pf[2];
    if (start + gstride < NUM_TILES) {
        const long nb = (long)(start + gstride) * TILE_M;
        #pragma unroll
        for (int p = 0; p < 2; p++) {
            const int i = p * THREADS + tid;
            pf[p] = *(const float4*)(x + (nb + (i >> 5)) * 256L + 4 * (i & 31));
        }
    }
    __syncthreads();

    int buf = 0;
    for (int t = start; t < NUM_TILES; t += gstride, buf ^= 1) {
        const long rowbase = (long)t * TILE_M;
        const int  t1 = t + gstride;          // next tile
        const int  t2 = t1 + gstride;         // tile after next
        const bool h1 = t1 < NUM_TILES;
        const bool h2 = t2 < NUM_TILES;

        // (a) Drain pf (x1 of t1, loaded LAST iteration): y1 STG + STS.
        if (h1) {
            const long nb = (long)t1 * TILE_M;
            uint32_t* Xn = XB[buf ^ 1];
            #pragma unroll
            for (int p = 0; p < 2; p++) {
                const int  i = p * THREADS + tid;
                const int  r = i >> 5;
                const int  q = i & 31;
                *(float4*)(out + (nb + r) * 256L + 4 * q) = pf[p];   // y1
                Xn[r * SA + 2 * q]     = bfpack(pf[p].x, pf[p].y);
                Xn[r * SA + 2 * q + 1] = bfpack(pf[p].z, pf[p].w);
            }
        }

        // (b) Issue x1 LDG for t2 (full-iteration cover until next drain).
        if (h2) {
            const long nb = (long)t2 * TILE_M;
            #pragma unroll
            for (int p = 0; p < 2; p++) {
                const int i = p * THREADS + tid;
                pf[p] = *(const float4*)(x + (nb + (i >> 5)) * 256L + 4 * (i & 31));
            }
        }

        // (c) Mainloop on tile t: B in regs, A via ldmatrix from XB[buf].
        float acc[2][4];
        #pragma unroll
        for (int j = 0; j < 2; j++)
            { acc[j][0] = 0.f; acc[j][1] = 0.f; acc[j][2] = 0.f; acc[j][3] = 0.f; }

        const uint32_t ab = buf ? ab1 : ab0;
        #pragma unroll
        for (int ks = 0; ks < 8; ks++) {
            uint32_t a0, a1, a2, a3;
            ldsm_x4(a0, a1, a2, a3, ab + ks * 32);
            #pragma unroll
            for (int j = 0; j < 2; j++) {
                mma_bf16(acc[j][0], acc[j][1], acc[j][2], acc[j][3],
                         a0, a1, a2, a3, Breg[ks][j][0], Breg[ks][j][1]);
            }
        }

        // (d) Epilogue: y2(t) = x2 + acc (x2 loaded last iteration).
        const long r0 = rowbase + gid;
        #pragma unroll
        for (int j = 0; j < 2; j++) {
            const long g0 = r0 * 256L + 128 + nbase + 8 * j + 2 * tig;
            float2 o0, o1;
            o0.x = x2a[j].x + acc[j][0];
            o0.y = x2a[j].y + acc[j][1];
            o1.x = x2b[j].x + acc[j][2];
            o1.y = x2b[j].y + acc[j][3];
            *(float2*)(out + g0) = o0;
            *(float2*)(out + g0 + 8 * 256L) = o1;
        }

        // (e) Prefetch x2 of t1 (consumed next iteration).
        if (h1) {
            const long r0n = (long)t1 * TILE_M + gid;
            #pragma unroll
            for (int j = 0; j < 2; j++) {
                const long g0 = r0n * 256L + 128 + nbase + 8 * j + 2 * tig;
                x2a[j] = *(const float2*)(x + g0);
                x2b[j] = *(const float2*)(x + g0 + 8 * 256L);
            }
        }

        // (f) Barrier: XB[buf^1] writes (a) visible to next iter's mainloop;
        //     this iter's XB[buf] reads (c) done before next iter's drain.
        __syncthreads();
    }
}

extern "C" void kernel_launch(void* const* d_in, const int* in_sizes, int n_in,
                              void* d_out, int out_size)
{
    const float* x = (const float*)d_in[0];   // [8, 32768, 256] fp32
    const float* w = (const float*)d_in[1];   // [128, 128] fp32
    float* out = (float*)d_out;

    cudaFuncSetAttribute(revnet_bf16_kernel,
                         cudaFuncAttributeMaxDynamicSharedMemorySize,
                         SMEM_BYTES);

    // 3 CTAs per SM, W frags in registers, 1-iteration-skewed x1 pipeline.
    revnet_bf16_kernel<<<444, THREADS, SMEM_BYTES>>>(x, w, out);
}